// round 15
// baseline (speedup 1.0000x reference)
#include <cuda_runtime.h>
#include <cuda_fp16.h>
#include <math.h>
#include <stdint.h>

#define NN 4096
#define GG 1024
#define HH1 512
#define HH2 64
#define NHEAD 4
#define CHAN 128
#define SEDIM 16
#define CAP 256
#define KP_DEC 128

// ---------------- scratch (static device globals; no allocation) ----------
__device__ __half g_A16[NN * GG];          // activations, single fp16
__device__ __half g_H16[NN * HH1];         // GAT pre-activation H, fp16
__device__ __half g_W1h[HH1 * GG],     g_W1l[HH1 * GG];      // enc1 [512][1024]
__device__ __half g_W2h[HH2 * HH1],    g_W2l[HH2 * HH1];     // enc2 [64][512]
__device__ __half g_W3h[HH1 * KP_DEC], g_W3l[HH1 * KP_DEC];  // dec1 [512][128]
__device__ __half g_W4h[GG * HH1],     g_W4l[GG * HH1];      // dec2 [1024][512]
__device__ float g_P0[NN * GG];            // split-K partials
__device__ float g_f1[NHEAD * NN];
__device__ float g_f2[NHEAD * NN];
__device__ int   g_cols[NN * CAP];
__device__ int   g_cnt[NN];

// ---------------- helpers ---------------------------------------------------
__device__ __forceinline__ void hsplit(float x, __half* h, __half* l) {
    __half hh = __float2half_rn(x);
    *h = hh;
    *l = __float2half_rn(x - __half2float(hh));
}
__device__ __forceinline__ uint32_t smem_u32(const void* p) {
    uint32_t a;
    asm("{ .reg .u64 t; cvta.to.shared.u64 t, %1; cvt.u32.u64 %0, t; }" : "=r"(a) : "l"(p));
    return a;
}
#define LDM4(r, addr) \
    asm volatile("ldmatrix.sync.aligned.m8n8.x4.shared.b16 {%0,%1,%2,%3}, [%4];" \
                 : "=r"((r)[0]), "=r"((r)[1]), "=r"((r)[2]), "=r"((r)[3]) : "r"(addr))
#define MMAF16(d, a, b0_, b1_) \
    asm volatile("mma.sync.aligned.m16n8k16.row.col.f32.f16.f16.f32 " \
                 "{%0,%1,%2,%3}, {%4,%5,%6,%7}, {%8,%9}, {%0,%1,%2,%3};" \
                 : "+f"((d)[0]), "+f"((d)[1]), "+f"((d)[2]), "+f"((d)[3]) \
                 : "r"((a)[0]), "r"((a)[1]), "r"((a)[2]), "r"((a)[3]), "r"(b0_), "r"(b1_))
#define CP16(dst, src) \
    asm volatile("cp.async.cg.shared.global [%0], [%1], 16;" :: "r"(dst), "l"(src))

// ---------------- fused prologue: csr + A16 convert + all weight packs -----
__global__ void __launch_bounds__(256) prologue(
    const float* __restrict__ adj, const float4* __restrict__ node,
    const float* __restrict__ enc1_W, const float* __restrict__ enc2_W,
    const float* __restrict__ dec1_W, const float* __restrict__ dec2_W) {
    __shared__ int cnt;
    int b = blockIdx.x, tid = threadIdx.x;
    if (b < 4096) {
        if (tid == 0) cnt = 0;
        __syncthreads();
        const float4* arow = (const float4*)(adj + (size_t)b * NN);
        for (int j4 = tid; j4 < NN / 4; j4 += 256) {
            float4 v = arow[j4];
            if (v.x != 0.f) { int k = atomicAdd(&cnt, 1); if (k < CAP) g_cols[b * CAP + k] = j4 * 4 + 0; }
            if (v.y != 0.f) { int k = atomicAdd(&cnt, 1); if (k < CAP) g_cols[b * CAP + k] = j4 * 4 + 1; }
            if (v.z != 0.f) { int k = atomicAdd(&cnt, 1); if (k < CAP) g_cols[b * CAP + k] = j4 * 4 + 2; }
            if (v.w != 0.f) { int k = atomicAdd(&cnt, 1); if (k < CAP) g_cols[b * CAP + k] = j4 * 4 + 3; }
        }
        __syncthreads();
        if (tid == 0) g_cnt[b] = min(cnt, CAP);
    } else if (b < 8192) {
        int i = (b - 4096) * 256 + tid;          // over NN*GG/4
        float4 v = node[i];
        __half2 h0 = __floats2half2_rn(v.x, v.y);
        __half2 h1 = __floats2half2_rn(v.z, v.w);
        uint2 u;
        u.x = *reinterpret_cast<uint32_t*>(&h0);
        u.y = *reinterpret_cast<uint32_t*>(&h1);
        *(uint2*)(g_A16 + (size_t)i * 4) = u;
    } else if (b < 10240) {
        int idx = (b - 8192) * 256 + tid;
        int n = idx >> 10, k = idx & 1023;
        float v = enc1_W[((size_t)(n >> 7) * GG + k) * CHAN + (n & 127)];
        hsplit(v, &g_W1h[idx], &g_W1l[idx]);
    } else if (b < 10368) {
        int idx = (b - 10240) * 256 + tid;
        int n = idx >> 9, k = idx & 511;
        hsplit(enc2_W[k * HH2 + n], &g_W2h[idx], &g_W2l[idx]);
    } else if (b < 10624) {
        int idx = (b - 10368) * 256 + tid;
        int n = idx >> 7, k = idx & 127;
        float v = (k < HH2 + SEDIM)
                      ? dec1_W[((size_t)(n >> 7) * (HH2 + SEDIM) + k) * CHAN + (n & 127)]
                      : 0.f;
        hsplit(v, &g_W3h[idx], &g_W3l[idx]);
    } else {
        int idx = (b - 10624) * 256 + tid;
        int n = idx >> 9, k = idx & 511;
        hsplit(dec2_W[(size_t)k * GG + n], &g_W4h[idx], &g_W4l[idx]);
    }
}

// ---------------- enc1 fused reduce: partials + bias -> H16 + f1/f2 --------
__global__ void __launch_bounds__(256) reduceF(
    const float4* __restrict__ P, const float4* __restrict__ bias,
    const float4* __restrict__ v0, const float4* __restrict__ v1) {
    const int idx = blockIdx.x * 256 + threadIdx.x;      // over NN*HH1/4
    const int row = idx >> 7, col4 = idx & 127;
    const int lid = threadIdx.x & 31;
    constexpr int T4 = NN * HH1 / 4;
    float4 s = P[idx];
    float4 q = P[idx + T4];
    s.x += q.x; s.y += q.y; s.z += q.z; s.w += q.w;
    float4 b = bias[col4];
    s.x += b.x; s.y += b.y; s.z += b.z; s.w += b.w;
    __half2 h0 = __floats2half2_rn(s.x, s.y);
    __half2 h1 = __floats2half2_rn(s.z, s.w);
    uint2 u;
    u.x = *reinterpret_cast<uint32_t*>(&h0);
    u.y = *reinterpret_cast<uint32_t*>(&h1);
    *(uint2*)(g_H16 + (size_t)idx * 4) = u;
    float4 a = v0[col4], c = v1[col4];
    float s1 = s.x * a.x + s.y * a.y + s.z * a.z + s.w * a.w;
    float s2 = s.x * c.x + s.y * c.y + s.z * c.z + s.w * c.w;
#pragma unroll
    for (int o = 16; o > 0; o >>= 1) {
        s1 += __shfl_down_sync(0xffffffffu, s1, o);
        s2 += __shfl_down_sync(0xffffffffu, s2, o);
    }
    if (lid == 0) {
        int h = col4 >> 5;
        g_f1[h * NN + row] = s1;
        g_f2[h * NN + row] = s2;
    }
}

// ---------------- fused Z reduce + decoder input build ---------------------
__global__ void __launch_bounds__(128) reduceZ(
    const float* __restrict__ P, const float* __restrict__ bias,
    float* __restrict__ outZ, const int* __restrict__ slice,
    const float* __restrict__ emb) {
    int n = blockIdx.x, t = threadIdx.x;   // 128 threads
    float v = 0.f;
    if (t < HH2) {
        int e = n * HH2 + t;
        v = P[e] + P[e + NN * HH2] + P[e + 2 * NN * HH2] + P[e + 3 * NN * HH2] + bias[t];
        outZ[e] = v;
    } else if (t < HH2 + SEDIM) {
        v = emb[slice[n] * SEDIM + (t - HH2)];
    }
    g_A16[(size_t)n * KP_DEC + t] = __float2half_rn(v);
}

// ---------------- HMMA fp16 2-term GEMM, 3-stage pipeline, 1 sync/chunk -----
// MODE 0: write C fp32 (+bias or raw partial).  MODE 2: write H16 only (+bias).
template <int MTILE, int NT, int MODE>
__global__ void __launch_bounds__(256, 2)
gemm2(const __half* __restrict__ A, const __half* __restrict__ Bh_,
      const __half* __restrict__ Bl_, const float* __restrict__ bias,
      float* __restrict__ C, int Kfull, int Ksplit, int Nc) {
    constexpr int WMW = 2;
    constexpr int WNW = 4;
    constexpr int WM  = MTILE / WMW;             // 64
    constexpr int WN  = NT / WNW;
    constexpr int MT  = WM / 16;                 // 4
    constexpr int NTL = WN / 8;
    constexpr int NP  = NTL / 2;
    constexpr int ASZ = MTILE * 80;
    constexpr int BSZ = NT * 80;
    constexpr int STG = ASZ + 2 * BSZ;
    constexpr int AJ  = MTILE / 64;              // 2
    constexpr int BJ  = NT / 64;

    extern __shared__ char sm[];
    const int tid = threadIdx.x, lane = tid & 31, wid = tid >> 5;
    const int m0 = blockIdx.y * MTILE, n0 = blockIdx.x * NT;
    const int koff = blockIdx.z * Ksplit;
    const int wm0 = (wid % WMW) * WM, wn0 = (wid / WMW) * WN;

    const int ar = tid >> 1, ac = (tid & 1) * 16;
    const size_t abase = (size_t)(m0 + ar) * Kfull + koff + ac;
    const int br = (BJ == 2) ? (tid >> 1) : (tid >> 2);
    const int bc = (BJ == 2) ? ((tid & 1) * 16) : ((tid & 3) * 8);
    const size_t bbase = (size_t)(n0 + br) * Kfull + koff + bc;

    const uint32_t sA = smem_u32(sm);
    const uint32_t stA = ar * 80 + ac * 2;
    const uint32_t stB = br * 80 + bc * 2;

    const int lr = lane & 15, lk = (lane >> 4) * 8;
    const uint32_t aoff = (wm0 + lr) * 80 + lk * 2;
    const uint32_t boff = (wn0 + lr) * 80 + lk * 2;

    float acc[MT][NTL][4];
#pragma unroll
    for (int i = 0; i < MT; i++)
#pragma unroll
        for (int j = 0; j < NTL; j++)
#pragma unroll
            for (int q = 0; q < 4; q++) acc[i][j][q] = 0.f;

    const int NC = Ksplit >> 5;

#define GLOADC(c0, buf)                                                        \
    {                                                                          \
        int k0 = (c0) * 32;                                                    \
        uint32_t d = sA + (buf) * STG;                                         \
        _Pragma("unroll") for (int j = 0; j < AJ; j++)                         \
            CP16(d + stA + j * 16, A + abase + k0 + j * 8);                    \
        _Pragma("unroll") for (int j = 0; j < BJ; j++) {                       \
            CP16(d + ASZ + stB + j * 16, Bh_ + bbase + k0 + j * 8);            \
            CP16(d + ASZ + BSZ + stB + j * 16, Bl_ + bbase + k0 + j * 8);      \
        }                                                                      \
        asm volatile("cp.async.commit_group;" ::: "memory");                   \
    }

    GLOADC(0, 0);
    GLOADC(1, 1);
    for (int c = 0; c < NC; c++) {
        if (c + 1 < NC) {
            asm volatile("cp.async.wait_group 1;" ::: "memory");
        } else {
            asm volatile("cp.async.wait_group 0;" ::: "memory");
        }
        __syncthreads();
        int buf = c % 3;
        uint32_t uA  = sA + buf * STG;
        uint32_t uBh = uA + ASZ;
        uint32_t uBl = uBh + BSZ;
#pragma unroll
        for (int ks = 0; ks < 2; ks++) {
            uint32_t a_[MT][4], bh[NP][4], bl[NP][4];
#pragma unroll
            for (int mt = 0; mt < MT; mt++) LDM4(a_[mt], uA + aoff + mt * 1280 + ks * 32);
#pragma unroll
            for (int p = 0; p < NP; p++) LDM4(bh[p], uBh + boff + p * 1280 + ks * 32);
#pragma unroll
            for (int p = 0; p < NP; p++) LDM4(bl[p], uBl + boff + p * 1280 + ks * 32);
#pragma unroll
            for (int mt = 0; mt < MT; mt++)
#pragma unroll
                for (int p = 0; p < NP; p++) {
                    MMAF16(acc[mt][2 * p],     a_[mt], bh[p][0], bh[p][2]);
                    MMAF16(acc[mt][2 * p + 1], a_[mt], bh[p][1], bh[p][3]);
                }
#pragma unroll
            for (int mt = 0; mt < MT; mt++)
#pragma unroll
                for (int p = 0; p < NP; p++) {
                    MMAF16(acc[mt][2 * p],     a_[mt], bl[p][0], bl[p][2]);
                    MMAF16(acc[mt][2 * p + 1], a_[mt], bl[p][1], bl[p][3]);
                }
        }
        if (c + 2 < NC) GLOADC(c + 2, (c + 2) % 3);
    }
#undef GLOADC

    // epilogue
    float* Cz = C + (size_t)blockIdx.z * NN * Nc;
    int g = lane >> 2, tg = lane & 3;
#pragma unroll
    for (int mt = 0; mt < MT; mt++) {
        int row = m0 + wm0 + mt * 16 + g;
#pragma unroll
        for (int nt = 0; nt < NTL; nt++) {
            int col = n0 + wn0 + nt * 8 + tg * 2;
            float b0 = bias ? bias[col] : 0.f, b1 = bias ? bias[col + 1] : 0.f;
            float c0 = acc[mt][nt][0] + b0, c1 = acc[mt][nt][1] + b1;
            float c2 = acc[mt][nt][2] + b0, c3 = acc[mt][nt][3] + b1;
            if (MODE == 0) {
                Cz[(size_t)row * Nc + col]           = c0;
                Cz[(size_t)row * Nc + col + 1]       = c1;
                Cz[(size_t)(row + 8) * Nc + col]     = c2;
                Cz[(size_t)(row + 8) * Nc + col + 1] = c3;
            } else {
                __half2 p0 = __floats2half2_rn(c0, c1);
                __half2 p1 = __floats2half2_rn(c2, c3);
                *(uint32_t*)(g_H16 + (size_t)row * Nc + col) =
                    *reinterpret_cast<uint32_t*>(&p0);
                *(uint32_t*)(g_H16 + (size_t)(row + 8) * Nc + col) =
                    *reinterpret_cast<uint32_t*>(&p1);
            }
        }
    }
}

// ---------------- attention features from fp16 H (dec path) ----------------
__global__ void __launch_bounds__(512) feats2h(const float* __restrict__ v0,
                                               const float* __restrict__ v1) {
    int tid = threadIdx.x, wid = tid >> 5, lid = tid & 31;
    int n = blockIdx.x * 4 + (wid >> 2);
    int h = wid & 3;
    uint2 uv = *(const uint2*)(g_H16 + (size_t)n * HH1 + h * CHAN + lid * 4);
    float2 f0 = __half22float2(*reinterpret_cast<__half2*>(&uv.x));
    float2 f1v = __half22float2(*reinterpret_cast<__half2*>(&uv.y));
    float4 a = *(const float4*)(v0 + h * CHAN + lid * 4);
    float4 b = *(const float4*)(v1 + h * CHAN + lid * 4);
    float s1 = f0.x * a.x + f0.y * a.y + f1v.x * a.z + f1v.y * a.w;
    float s2 = f0.x * b.x + f0.y * b.y + f1v.x * b.z + f1v.y * b.w;
#pragma unroll
    for (int o = 16; o > 0; o >>= 1) {
        s1 += __shfl_down_sync(0xffffffffu, s1, o);
        s2 += __shfl_down_sync(0xffffffffu, s2, o);
    }
    if (lid == 0) {
        g_f1[h * NN + n] = s1;
        g_f2[h * NN + n] = s2;
    }
}

// ---------------- sparse attention softmax + aggregation + ELU -------------
// warp = one (row, head); fast path: 2 neighbors/iter, uint4 gathers
__global__ void __launch_bounds__(128) gat_agg5() {
    int row = blockIdx.x, tid = threadIdx.x, wid = tid >> 5, lid = tid & 31;
    int cnt = g_cnt[row];
    const int* cols = g_cols + row * CAP;
    const float* f2h = g_f2 + wid * NN;
    float f1r = g_f1[wid * NN + row];

    if (cnt <= 32) {
        bool valid = lid < cnt;
        int col = valid ? cols[lid] : 0;
        float u = 0.f;
        if (valid) {
            float x = f1r + f2h[col];
            u = 1.f / (1.f + expf(-x)) - 0.5f;
        }
        float mv = (valid && u != 0.f) ? u : -1e30f;
#pragma unroll
        for (int o = 16; o; o >>= 1) mv = fmaxf(mv, __shfl_xor_sync(0xffffffffu, mv, o));
        float e = (valid && u != 0.f) ? expf(u - mv) : 0.f;
        float s = e;
#pragma unroll
        for (int o = 16; o; o >>= 1) s += __shfl_xor_sync(0xffffffffu, s, o);
        float inv = 1.f / fmaxf(s, 1e-30f);
        uint32_t pk = ((uint32_t)__half_as_ushort(__float2half_rn(e)) << 16) |
                      (uint32_t)col;
        // lanes 0-15 handle even neighbors, 16-31 odd; 8 channels per lane
        int half_ = lid >> 4;
        int ch8 = (lid & 15) * 8;
        const __half* Hb2 = g_H16 + wid * CHAN + ch8;
        float av[8];
#pragma unroll
        for (int j = 0; j < 8; j++) av[j] = 0.f;
        for (int k = 0; k < cnt; k += 2) {
            uint32_t p = __shfl_sync(0xffffffffu, pk, k + half_);
            if (p >> 16) {
                float w = __half2float(__ushort_as_half((unsigned short)(p >> 16)));
                int c2 = p & 0xFFFF;
                uint4 uv = *(const uint4*)(Hb2 + (size_t)c2 * HH1);
                const __half2* hp = reinterpret_cast<const __half2*>(&uv);
#pragma unroll
                for (int j = 0; j < 4; j++) {
                    float2 f = __half22float2(hp[j]);
                    av[2 * j]     += w * f.x;
                    av[2 * j + 1] += w * f.y;
                }
            }
        }
#pragma unroll
        for (int j = 0; j < 8; j++) av[j] += __shfl_xor_sync(0xffffffffu, av[j], 16);
        if (lid < 16) {
            __half2 q[4];
#pragma unroll
            for (int j = 0; j < 4; j++) {
                float x0 = av[2 * j] * inv, x1 = av[2 * j + 1] * inv;
                x0 = (x0 > 0.f) ? x0 : expm1f(x0);
                x1 = (x1 > 0.f) ? x1 : expm1f(x1);
                q[j] = __floats2half2_rn(x0, x1);
            }
            *(uint4*)(g_A16 + (size_t)row * HH1 + wid * CHAN + ch8) =
                *reinterpret_cast<uint4*>(q);
        }
    } else {
        // general path (rare): scalar, 3 passes
        const __half* Hb = g_H16 + wid * CHAN + lid * 4;
        float4 acc = {0.f, 0.f, 0.f, 0.f};
        float mv = -1e30f;
        for (int c0 = 0; c0 < cnt; c0 += 32) {
            int k = c0 + lid;
            if (k < cnt) {
                float x = f1r + f2h[cols[k]];
                float u = 1.f / (1.f + expf(-x)) - 0.5f;
                if (u != 0.f) mv = fmaxf(mv, u);
            }
        }
#pragma unroll
        for (int o = 16; o; o >>= 1) mv = fmaxf(mv, __shfl_xor_sync(0xffffffffu, mv, o));
        float s = 0.f;
        for (int c0 = 0; c0 < cnt; c0 += 32) {
            int k = c0 + lid;
            if (k < cnt) {
                float x = f1r + f2h[cols[k]];
                float u = 1.f / (1.f + expf(-x)) - 0.5f;
                if (u != 0.f) s += expf(u - mv);
            }
        }
#pragma unroll
        for (int o = 16; o; o >>= 1) s += __shfl_xor_sync(0xffffffffu, s, o);
        float inv = 1.f / fmaxf(s, 1e-30f);
        for (int c0 = 0; c0 < cnt; c0 += 32) {
            int k = c0 + lid;
            int col = (k < cnt) ? cols[k] : 0;
            float e = 0.f;
            if (k < cnt) {
                float x = f1r + f2h[col];
                float u = 1.f / (1.f + expf(-x)) - 0.5f;
                if (u != 0.f) e = expf(u - mv);
            }
            int lim = min(32, cnt - c0);
            for (int j = 0; j < lim; j++) {
                float w = __shfl_sync(0xffffffffu, e, j);
                int c2 = __shfl_sync(0xffffffffu, col, j);
                if (w != 0.f) {
                    uint2 uv = *(const uint2*)(Hb + (size_t)c2 * HH1);
                    float2 f0 = __half22float2(*reinterpret_cast<__half2*>(&uv.x));
                    float2 f1v = __half22float2(*reinterpret_cast<__half2*>(&uv.y));
                    acc.x += w * f0.x; acc.y += w * f0.y;
                    acc.z += w * f1v.x; acc.w += w * f1v.y;
                }
            }
        }
        acc.x *= inv; acc.y *= inv; acc.z *= inv; acc.w *= inv;
        acc.x = (acc.x > 0.f) ? acc.x : expm1f(acc.x);
        acc.y = (acc.y > 0.f) ? acc.y : expm1f(acc.y);
        acc.z = (acc.z > 0.f) ? acc.z : expm1f(acc.z);
        acc.w = (acc.w > 0.f) ? acc.w : expm1f(acc.w);
        __half2 p0 = __floats2half2_rn(acc.x, acc.y);
        __half2 p1 = __floats2half2_rn(acc.z, acc.w);
        uint2 u;
        u.x = *reinterpret_cast<uint32_t*>(&p0);
        u.y = *reinterpret_cast<uint32_t*>(&p1);
        *(uint2*)(g_A16 + (size_t)row * HH1 + wid * CHAN + lid * 4) = u;
    }
}

extern "C" void kernel_launch(void* const* d_in, const int* in_sizes, int n_in,
                              void* d_out, int out_size) {
    const float* adj     = (const float*)d_in[0];
    const float* node    = (const float*)d_in[1];
    const int*   slice   = (const int*)d_in[4];
    const float* enc1_W  = (const float*)d_in[6];
    const float* enc1_b  = (const float*)d_in[7];
    const float* enc1_v0 = (const float*)d_in[8];
    const float* enc1_v1 = (const float*)d_in[9];
    const float* enc2_W  = (const float*)d_in[10];
    const float* enc2_b  = (const float*)d_in[11];
    const float* dec1_W  = (const float*)d_in[12];
    const float* dec1_b  = (const float*)d_in[13];
    const float* dec1_v0 = (const float*)d_in[14];
    const float* dec1_v1 = (const float*)d_in[15];
    const float* dec2_W  = (const float*)d_in[16];
    const float* dec2_b  = (const float*)d_in[17];
    const float* emb     = (const float*)d_in[18];

    float* out_recon = (float*)d_out;                   // [N, G]
    float* out_Z     = (float*)d_out + (size_t)NN * GG; // [N, H2]

    float* P0;   cudaGetSymbolAddress((void**)&P0, g_P0);
    __half* A16; cudaGetSymbolAddress((void**)&A16, g_A16);
    __half* W1h; cudaGetSymbolAddress((void**)&W1h, g_W1h);
    __half* W1l; cudaGetSymbolAddress((void**)&W1l, g_W1l);
    __half* W2h; cudaGetSymbolAddress((void**)&W2h, g_W2h);
    __half* W2l; cudaGetSymbolAddress((void**)&W2l, g_W2l);
    __half* W3h; cudaGetSymbolAddress((void**)&W3h, g_W3h);
    __half* W3l; cudaGetSymbolAddress((void**)&W3l, g_W3l);
    __half* W4h; cudaGetSymbolAddress((void**)&W4h, g_W4h);
    __half* W4l; cudaGetSymbolAddress((void**)&W4l, g_W4l);

    const int SM128 = 3 * (128 * 80 + 2 * 128 * 80); // 92160
    const int SM64  = 3 * (128 * 80 + 2 * 64 * 80);  // 61440
    cudaFuncSetAttribute((const void*)gemm2<128, 128, 0>,
                         cudaFuncAttributeMaxDynamicSharedMemorySize, SM128);
    cudaFuncSetAttribute((const void*)gemm2<128, 128, 2>,
                         cudaFuncAttributeMaxDynamicSharedMemorySize, SM128);
    cudaFuncSetAttribute((const void*)gemm2<128, 64, 0>,
                         cudaFuncAttributeMaxDynamicSharedMemorySize, SM64);

    // 0. fused prologue: CSR + fp16 convert + all weight packs
    prologue<<<12672, 256>>>(adj, (const float4*)node,
                             enc1_W, enc2_W, dec1_W, dec2_W);

    // 1. enc1 GEMM (K=1024, split-K=2) + fused reduce->H16 + feats
    gemm2<128, 128, 0><<<dim3(4, 32, 2), 256, SM128>>>(
        A16, W1h, W1l, nullptr, P0, GG, GG / 2, HH1);
    reduceF<<<NN * HH1 / 4 / 256, 256>>>(
        (const float4*)P0, (const float4*)enc1_b,
        (const float4*)enc1_v0, (const float4*)enc1_v1);
    gat_agg5<<<NN, 128>>>();   // H16 -> g_A16 [4096,512] fp16

    // 2. Z GEMM (K=512, split-K=4) + fused reduce -> out_Z + decoder input
    gemm2<128, 64, 0><<<dim3(1, 32, 4), 256, SM64>>>(
        A16, W2h, W2l, nullptr, P0, HH1, HH1 / 4, HH2);
    reduceZ<<<NN, 128>>>(P0, enc2_b, out_Z, slice, emb);

    // 3. decoder GAT layer (K=128): GEMM writes H16 only
    gemm2<128, 128, 2><<<dim3(4, 32, 1), 256, SM128>>>(
        A16, W3h, W3l, dec1_b, nullptr, KP_DEC, KP_DEC, HH1);
    feats2h<<<NN / 4, 512>>>(dec1_v0, dec1_v1);
    gat_agg5<<<NN, 128>>>();   // H16 -> g_A16 [4096,512]

    // 4. recon GEMM (K=512)
    gemm2<128, 128, 0><<<dim3(8, 32, 1), 256, SM128>>>(
        A16, W4h, W4l, dec2_b, out_recon, HH1, HH1, GG);
}

// round 16
// speedup vs baseline: 1.0202x; 1.0202x over previous
#include <cuda_runtime.h>
#include <cuda_fp16.h>
#include <math.h>
#include <stdint.h>

#define NN 4096
#define GG 1024
#define HH1 512
#define HH2 64
#define NHEAD 4
#define CHAN 128
#define SEDIM 16
#define CAP 256
#define KP_DEC 128

// ---------------- scratch (static device globals; no allocation) ----------
__device__ __half g_A16[NN * GG];          // activations, single fp16
__device__ __half g_H16[NN * HH1];         // GAT pre-activation H, fp16
__device__ __half g_W1h[HH1 * GG],     g_W1l[HH1 * GG];      // enc1 [512][1024]
__device__ __half g_W2h[HH2 * HH1],    g_W2l[HH2 * HH1];     // enc2 [64][512]
__device__ __half g_W3h[HH1 * KP_DEC], g_W3l[HH1 * KP_DEC];  // dec1 [512][128]
__device__ __half g_W4h[GG * HH1],     g_W4l[GG * HH1];      // dec2 [1024][512]
__device__ float g_P0[NN * GG];            // split-K partials (Z GEMM)
__device__ float g_f1[NHEAD * NN];
__device__ float g_f2[NHEAD * NN];
__device__ int   g_cols[NN * CAP];
__device__ int   g_cnt[NN];

// ---------------- helpers ---------------------------------------------------
__device__ __forceinline__ void hsplit(float x, __half* h, __half* l) {
    __half hh = __float2half_rn(x);
    *h = hh;
    *l = __float2half_rn(x - __half2float(hh));
}
__device__ __forceinline__ uint32_t smem_u32(const void* p) {
    uint32_t a;
    asm("{ .reg .u64 t; cvta.to.shared.u64 t, %1; cvt.u32.u64 %0, t; }" : "=r"(a) : "l"(p));
    return a;
}
#define LDM4(r, addr) \
    asm volatile("ldmatrix.sync.aligned.m8n8.x4.shared.b16 {%0,%1,%2,%3}, [%4];" \
                 : "=r"((r)[0]), "=r"((r)[1]), "=r"((r)[2]), "=r"((r)[3]) : "r"(addr))
#define MMAF16(d, a, b0_, b1_) \
    asm volatile("mma.sync.aligned.m16n8k16.row.col.f32.f16.f16.f32 " \
                 "{%0,%1,%2,%3}, {%4,%5,%6,%7}, {%8,%9}, {%0,%1,%2,%3};" \
                 : "+f"((d)[0]), "+f"((d)[1]), "+f"((d)[2]), "+f"((d)[3]) \
                 : "r"((a)[0]), "r"((a)[1]), "r"((a)[2]), "r"((a)[3]), "r"(b0_), "r"(b1_))
#define CP16(dst, src) \
    asm volatile("cp.async.cg.shared.global [%0], [%1], 16;" :: "r"(dst), "l"(src))

// ---------------- fused prologue: csr + A16 convert + all weight packs -----
__global__ void __launch_bounds__(256) prologue(
    const float* __restrict__ adj, const float4* __restrict__ node,
    const float* __restrict__ enc1_W, const float* __restrict__ enc2_W,
    const float* __restrict__ dec1_W, const float* __restrict__ dec2_W) {
    __shared__ int cnt;
    int b = blockIdx.x, tid = threadIdx.x;
    if (b < 4096) {
        if (tid == 0) cnt = 0;
        __syncthreads();
        const float4* arow = (const float4*)(adj + (size_t)b * NN);
        for (int j4 = tid; j4 < NN / 4; j4 += 256) {
            float4 v = arow[j4];
            if (v.x != 0.f) { int k = atomicAdd(&cnt, 1); if (k < CAP) g_cols[b * CAP + k] = j4 * 4 + 0; }
            if (v.y != 0.f) { int k = atomicAdd(&cnt, 1); if (k < CAP) g_cols[b * CAP + k] = j4 * 4 + 1; }
            if (v.z != 0.f) { int k = atomicAdd(&cnt, 1); if (k < CAP) g_cols[b * CAP + k] = j4 * 4 + 2; }
            if (v.w != 0.f) { int k = atomicAdd(&cnt, 1); if (k < CAP) g_cols[b * CAP + k] = j4 * 4 + 3; }
        }
        __syncthreads();
        if (tid == 0) g_cnt[b] = min(cnt, CAP);
    } else if (b < 8192) {
        int i = (b - 4096) * 256 + tid;          // over NN*GG/4
        float4 v = node[i];
        __half2 h0 = __floats2half2_rn(v.x, v.y);
        __half2 h1 = __floats2half2_rn(v.z, v.w);
        uint2 u;
        u.x = *reinterpret_cast<uint32_t*>(&h0);
        u.y = *reinterpret_cast<uint32_t*>(&h1);
        *(uint2*)(g_A16 + (size_t)i * 4) = u;
    } else if (b < 10240) {
        int idx = (b - 8192) * 256 + tid;
        int n = idx >> 10, k = idx & 1023;
        float v = enc1_W[((size_t)(n >> 7) * GG + k) * CHAN + (n & 127)];
        hsplit(v, &g_W1h[idx], &g_W1l[idx]);
    } else if (b < 10368) {
        int idx = (b - 10240) * 256 + tid;
        int n = idx >> 9, k = idx & 511;
        hsplit(enc2_W[k * HH2 + n], &g_W2h[idx], &g_W2l[idx]);
    } else if (b < 10624) {
        int idx = (b - 10368) * 256 + tid;
        int n = idx >> 7, k = idx & 127;
        float v = (k < HH2 + SEDIM)
                      ? dec1_W[((size_t)(n >> 7) * (HH2 + SEDIM) + k) * CHAN + (n & 127)]
                      : 0.f;
        hsplit(v, &g_W3h[idx], &g_W3l[idx]);
    } else {
        int idx = (b - 10624) * 256 + tid;
        int n = idx >> 9, k = idx & 511;
        hsplit(dec2_W[(size_t)k * GG + n], &g_W4h[idx], &g_W4l[idx]);
    }
}

// ---------------- fused Z reduce + decoder input build ---------------------
__global__ void __launch_bounds__(128) reduceZ(
    const float* __restrict__ P, const float* __restrict__ bias,
    float* __restrict__ outZ, const int* __restrict__ slice,
    const float* __restrict__ emb) {
    int n = blockIdx.x, t = threadIdx.x;   // 128 threads
    float v = 0.f;
    if (t < HH2) {
        int e = n * HH2 + t;
        v = P[e] + P[e + NN * HH2] + P[e + 2 * NN * HH2] + P[e + 3 * NN * HH2] + bias[t];
        outZ[e] = v;
    } else if (t < HH2 + SEDIM) {
        v = emb[slice[n] * SEDIM + (t - HH2)];
    }
    g_A16[(size_t)n * KP_DEC + t] = __float2half_rn(v);
}

// ---------------- HMMA fp16 2-term GEMM, 3-stage pipeline, 1 sync/chunk -----
// MODE 0: write C fp32 (+bias or raw partial).  MODE 2: write H16 only (+bias).
template <int MTILE, int NT, int MODE>
__global__ void __launch_bounds__(256, 2)
gemm2(const __half* __restrict__ A, const __half* __restrict__ Bh_,
      const __half* __restrict__ Bl_, const float* __restrict__ bias,
      float* __restrict__ C, int Kfull, int Ksplit, int Nc) {
    constexpr int WMW = 2;
    constexpr int WNW = 4;
    constexpr int WM  = MTILE / WMW;             // 64
    constexpr int WN  = NT / WNW;
    constexpr int MT  = WM / 16;                 // 4
    constexpr int NTL = WN / 8;
    constexpr int NP  = NTL / 2;
    constexpr int ASZ = MTILE * 80;
    constexpr int BSZ = NT * 80;
    constexpr int STG = ASZ + 2 * BSZ;
    constexpr int AJ  = MTILE / 64;              // 2
    constexpr int BJ  = NT / 64;

    extern __shared__ char sm[];
    const int tid = threadIdx.x, lane = tid & 31, wid = tid >> 5;
    const int m0 = blockIdx.y * MTILE, n0 = blockIdx.x * NT;
    const int koff = blockIdx.z * Ksplit;
    const int wm0 = (wid % WMW) * WM, wn0 = (wid / WMW) * WN;

    const int ar = tid >> 1, ac = (tid & 1) * 16;
    const size_t abase = (size_t)(m0 + ar) * Kfull + koff + ac;
    const int br = (BJ == 2) ? (tid >> 1) : (tid >> 2);
    const int bc = (BJ == 2) ? ((tid & 1) * 16) : ((tid & 3) * 8);
    const size_t bbase = (size_t)(n0 + br) * Kfull + koff + bc;

    const uint32_t sA = smem_u32(sm);
    const uint32_t stA = ar * 80 + ac * 2;
    const uint32_t stB = br * 80 + bc * 2;

    const int lr = lane & 15, lk = (lane >> 4) * 8;
    const uint32_t aoff = (wm0 + lr) * 80 + lk * 2;
    const uint32_t boff = (wn0 + lr) * 80 + lk * 2;

    float acc[MT][NTL][4];
#pragma unroll
    for (int i = 0; i < MT; i++)
#pragma unroll
        for (int j = 0; j < NTL; j++)
#pragma unroll
            for (int q = 0; q < 4; q++) acc[i][j][q] = 0.f;

    const int NC = Ksplit >> 5;

#define GLOADC(c0, buf)                                                        \
    {                                                                          \
        int k0 = (c0) * 32;                                                    \
        uint32_t d = sA + (buf) * STG;                                         \
        _Pragma("unroll") for (int j = 0; j < AJ; j++)                         \
            CP16(d + stA + j * 16, A + abase + k0 + j * 8);                    \
        _Pragma("unroll") for (int j = 0; j < BJ; j++) {                       \
            CP16(d + ASZ + stB + j * 16, Bh_ + bbase + k0 + j * 8);            \
            CP16(d + ASZ + BSZ + stB + j * 16, Bl_ + bbase + k0 + j * 8);      \
        }                                                                      \
        asm volatile("cp.async.commit_group;" ::: "memory");                   \
    }

    GLOADC(0, 0);
    GLOADC(1, 1);
    for (int c = 0; c < NC; c++) {
        if (c + 1 < NC) {
            asm volatile("cp.async.wait_group 1;" ::: "memory");
        } else {
            asm volatile("cp.async.wait_group 0;" ::: "memory");
        }
        __syncthreads();
        int buf = c % 3;
        uint32_t uA  = sA + buf * STG;
        uint32_t uBh = uA + ASZ;
        uint32_t uBl = uBh + BSZ;
#pragma unroll
        for (int ks = 0; ks < 2; ks++) {
            uint32_t a_[MT][4], bh[NP][4], bl[NP][4];
#pragma unroll
            for (int mt = 0; mt < MT; mt++) LDM4(a_[mt], uA + aoff + mt * 1280 + ks * 32);
#pragma unroll
            for (int p = 0; p < NP; p++) LDM4(bh[p], uBh + boff + p * 1280 + ks * 32);
#pragma unroll
            for (int p = 0; p < NP; p++) LDM4(bl[p], uBl + boff + p * 1280 + ks * 32);
#pragma unroll
            for (int mt = 0; mt < MT; mt++)
#pragma unroll
                for (int p = 0; p < NP; p++) {
                    MMAF16(acc[mt][2 * p],     a_[mt], bh[p][0], bh[p][2]);
                    MMAF16(acc[mt][2 * p + 1], a_[mt], bh[p][1], bh[p][3]);
                }
#pragma unroll
            for (int mt = 0; mt < MT; mt++)
#pragma unroll
                for (int p = 0; p < NP; p++) {
                    MMAF16(acc[mt][2 * p],     a_[mt], bl[p][0], bl[p][2]);
                    MMAF16(acc[mt][2 * p + 1], a_[mt], bl[p][1], bl[p][3]);
                }
        }
        if (c + 2 < NC) GLOADC(c + 2, (c + 2) % 3);
    }
#undef GLOADC

    // epilogue
    float* Cz = C + (size_t)blockIdx.z * NN * Nc;
    int g = lane >> 2, tg = lane & 3;
#pragma unroll
    for (int mt = 0; mt < MT; mt++) {
        int row = m0 + wm0 + mt * 16 + g;
#pragma unroll
        for (int nt = 0; nt < NTL; nt++) {
            int col = n0 + wn0 + nt * 8 + tg * 2;
            float b0 = bias ? bias[col] : 0.f, b1 = bias ? bias[col + 1] : 0.f;
            float c0 = acc[mt][nt][0] + b0, c1 = acc[mt][nt][1] + b1;
            float c2 = acc[mt][nt][2] + b0, c3 = acc[mt][nt][3] + b1;
            if (MODE == 0) {
                Cz[(size_t)row * Nc + col]           = c0;
                Cz[(size_t)row * Nc + col + 1]       = c1;
                Cz[(size_t)(row + 8) * Nc + col]     = c2;
                Cz[(size_t)(row + 8) * Nc + col + 1] = c3;
            } else {
                __half2 p0 = __floats2half2_rn(c0, c1);
                __half2 p1 = __floats2half2_rn(c2, c3);
                *(uint32_t*)(g_H16 + (size_t)row * Nc + col) =
                    *reinterpret_cast<uint32_t*>(&p0);
                *(uint32_t*)(g_H16 + (size_t)(row + 8) * Nc + col) =
                    *reinterpret_cast<uint32_t*>(&p1);
            }
        }
    }
}

// ---------------- attention features from fp16 H ---------------------------
__global__ void __launch_bounds__(512) feats2h(const float* __restrict__ v0,
                                               const float* __restrict__ v1) {
    int tid = threadIdx.x, wid = tid >> 5, lid = tid & 31;
    int n = blockIdx.x * 4 + (wid >> 2);
    int h = wid & 3;
    uint2 uv = *(const uint2*)(g_H16 + (size_t)n * HH1 + h * CHAN + lid * 4);
    float2 f0 = __half22float2(*reinterpret_cast<__half2*>(&uv.x));
    float2 f1v = __half22float2(*reinterpret_cast<__half2*>(&uv.y));
    float4 a = *(const float4*)(v0 + h * CHAN + lid * 4);
    float4 b = *(const float4*)(v1 + h * CHAN + lid * 4);
    float s1 = f0.x * a.x + f0.y * a.y + f1v.x * a.z + f1v.y * a.w;
    float s2 = f0.x * b.x + f0.y * b.y + f1v.x * b.z + f1v.y * b.w;
#pragma unroll
    for (int o = 16; o > 0; o >>= 1) {
        s1 += __shfl_down_sync(0xffffffffu, s1, o);
        s2 += __shfl_down_sync(0xffffffffu, s2, o);
    }
    if (lid == 0) {
        g_f1[h * NN + n] = s1;
        g_f2[h * NN + n] = s2;
    }
}

// ---------------- sparse attention softmax + aggregation + ELU -------------
__global__ void __launch_bounds__(128) gat_agg4() {
    int row = blockIdx.x, tid = threadIdx.x, wid = tid >> 5, lid = tid & 31;
    int cnt = g_cnt[row];
    const int* cols = g_cols + row * CAP;
    const float* f2h = g_f2 + wid * NN;
    float f1r = g_f1[wid * NN + row];
    const __half* Hb = g_H16 + wid * CHAN + lid * 4;
    float4 acc = {0.f, 0.f, 0.f, 0.f};
    float inv;

    if (cnt <= 32) {
        bool valid = lid < cnt;
        int col = valid ? cols[lid] : 0;
        float u = 0.f;
        if (valid) {
            float x = f1r + f2h[col];
            u = 1.f / (1.f + expf(-x)) - 0.5f;
        }
        float mv = (valid && u != 0.f) ? u : -1e30f;
#pragma unroll
        for (int o = 16; o; o >>= 1) mv = fmaxf(mv, __shfl_xor_sync(0xffffffffu, mv, o));
        float e = (valid && u != 0.f) ? expf(u - mv) : 0.f;
        float s = e;
#pragma unroll
        for (int o = 16; o; o >>= 1) s += __shfl_xor_sync(0xffffffffu, s, o);
        inv = 1.f / fmaxf(s, 1e-30f);
        uint32_t pk = ((uint32_t)__half_as_ushort(__float2half_rn(e)) << 16) |
                      (uint32_t)col;
        for (int k = 0; k < cnt; k++) {
            uint32_t p = __shfl_sync(0xffffffffu, pk, k);
            if (p >> 16) {
                float w = __half2float(__ushort_as_half((unsigned short)(p >> 16)));
                int c2 = p & 0xFFFF;
                uint2 uv = *(const uint2*)(Hb + (size_t)c2 * HH1);
                float2 f0 = __half22float2(*reinterpret_cast<__half2*>(&uv.x));
                float2 f1v = __half22float2(*reinterpret_cast<__half2*>(&uv.y));
                acc.x += w * f0.x; acc.y += w * f0.y;
                acc.z += w * f1v.x; acc.w += w * f1v.y;
            }
        }
    } else {
        float mv = -1e30f;
        for (int c0 = 0; c0 < cnt; c0 += 32) {
            int k = c0 + lid;
            if (k < cnt) {
                float x = f1r + f2h[cols[k]];
                float u = 1.f / (1.f + expf(-x)) - 0.5f;
                if (u != 0.f) mv = fmaxf(mv, u);
            }
        }
#pragma unroll
        for (int o = 16; o; o >>= 1) mv = fmaxf(mv, __shfl_xor_sync(0xffffffffu, mv, o));
        float s = 0.f;
        for (int c0 = 0; c0 < cnt; c0 += 32) {
            int k = c0 + lid;
            if (k < cnt) {
                float x = f1r + f2h[cols[k]];
                float u = 1.f / (1.f + expf(-x)) - 0.5f;
                if (u != 0.f) s += expf(u - mv);
            }
        }
#pragma unroll
        for (int o = 16; o; o >>= 1) s += __shfl_xor_sync(0xffffffffu, s, o);
        inv = 1.f / fmaxf(s, 1e-30f);
        for (int c0 = 0; c0 < cnt; c0 += 32) {
            int k = c0 + lid;
            int col = (k < cnt) ? cols[k] : 0;
            float e = 0.f;
            if (k < cnt) {
                float x = f1r + f2h[col];
                float u = 1.f / (1.f + expf(-x)) - 0.5f;
                if (u != 0.f) e = expf(u - mv);
            }
            int lim = min(32, cnt - c0);
            for (int j = 0; j < lim; j++) {
                float w = __shfl_sync(0xffffffffu, e, j);
                int c2 = __shfl_sync(0xffffffffu, col, j);
                if (w != 0.f) {
                    uint2 uv = *(const uint2*)(Hb + (size_t)c2 * HH1);
                    float2 f0 = __half22float2(*reinterpret_cast<__half2*>(&uv.x));
                    float2 f1v = __half22float2(*reinterpret_cast<__half2*>(&uv.y));
                    acc.x += w * f0.x; acc.y += w * f0.y;
                    acc.z += w * f1v.x; acc.w += w * f1v.y;
                }
            }
        }
    }

    acc.x *= inv; acc.y *= inv; acc.z *= inv; acc.w *= inv;
    acc.x = (acc.x > 0.f) ? acc.x : expm1f(acc.x);
    acc.y = (acc.y > 0.f) ? acc.y : expm1f(acc.y);
    acc.z = (acc.z > 0.f) ? acc.z : expm1f(acc.z);
    acc.w = (acc.w > 0.f) ? acc.w : expm1f(acc.w);
    __half2 p0 = __floats2half2_rn(acc.x, acc.y);
    __half2 p1 = __floats2half2_rn(acc.z, acc.w);
    uint2 u;
    u.x = *reinterpret_cast<uint32_t*>(&p0);
    u.y = *reinterpret_cast<uint32_t*>(&p1);
    *(uint2*)(g_A16 + (size_t)row * HH1 + wid * CHAN + lid * 4) = u;
}

extern "C" void kernel_launch(void* const* d_in, const int* in_sizes, int n_in,
                              void* d_out, int out_size) {
    const float* adj     = (const float*)d_in[0];
    const float* node    = (const float*)d_in[1];
    const int*   slice   = (const int*)d_in[4];
    const float* enc1_W  = (const float*)d_in[6];
    const float* enc1_b  = (const float*)d_in[7];
    const float* enc1_v0 = (const float*)d_in[8];
    const float* enc1_v1 = (const float*)d_in[9];
    const float* enc2_W  = (const float*)d_in[10];
    const float* enc2_b  = (const float*)d_in[11];
    const float* dec1_W  = (const float*)d_in[12];
    const float* dec1_b  = (const float*)d_in[13];
    const float* dec1_v0 = (const float*)d_in[14];
    const float* dec1_v1 = (const float*)d_in[15];
    const float* dec2_W  = (const float*)d_in[16];
    const float* dec2_b  = (const float*)d_in[17];
    const float* emb     = (const float*)d_in[18];

    float* out_recon = (float*)d_out;                   // [N, G]
    float* out_Z     = (float*)d_out + (size_t)NN * GG; // [N, H2]

    float* P0;   cudaGetSymbolAddress((void**)&P0, g_P0);
    __half* A16; cudaGetSymbolAddress((void**)&A16, g_A16);
    __half* W1h; cudaGetSymbolAddress((void**)&W1h, g_W1h);
    __half* W1l; cudaGetSymbolAddress((void**)&W1l, g_W1l);
    __half* W2h; cudaGetSymbolAddress((void**)&W2h, g_W2h);
    __half* W2l; cudaGetSymbolAddress((void**)&W2l, g_W2l);
    __half* W3h; cudaGetSymbolAddress((void**)&W3h, g_W3h);
    __half* W3l; cudaGetSymbolAddress((void**)&W3l, g_W3l);
    __half* W4h; cudaGetSymbolAddress((void**)&W4h, g_W4h);
    __half* W4l; cudaGetSymbolAddress((void**)&W4l, g_W4l);

    const int SM128 = 3 * (128 * 80 + 2 * 128 * 80); // 92160
    const int SM64  = 3 * (128 * 80 + 2 * 64 * 80);  // 61440
    cudaFuncSetAttribute((const void*)gemm2<128, 128, 0>,
                         cudaFuncAttributeMaxDynamicSharedMemorySize, SM128);
    cudaFuncSetAttribute((const void*)gemm2<128, 128, 2>,
                         cudaFuncAttributeMaxDynamicSharedMemorySize, SM128);
    cudaFuncSetAttribute((const void*)gemm2<128, 64, 0>,
                         cudaFuncAttributeMaxDynamicSharedMemorySize, SM64);

    // 0. fused prologue: CSR + fp16 convert + all weight packs
    prologue<<<12672, 256>>>(adj, (const float4*)node,
                             enc1_W, enc2_W, dec1_W, dec2_W);

    // 1. enc1 GEMM (K=1024, no split-K) -> H16; feats from H16 (dec pattern)
    gemm2<128, 128, 2><<<dim3(4, 32, 1), 256, SM128>>>(
        A16, W1h, W1l, enc1_b, nullptr, GG, GG, HH1);
    feats2h<<<NN / 4, 512>>>(enc1_v0, enc1_v1);
    gat_agg4<<<NN, 128>>>();   // H16 -> g_A16 [4096,512] fp16

    // 2. Z GEMM (K=512, split-K=4) + fused reduce -> out_Z + decoder input
    gemm2<128, 64, 0><<<dim3(1, 32, 4), 256, SM64>>>(
        A16, W2h, W2l, nullptr, P0, HH1, HH1 / 4, HH2);
    reduceZ<<<NN, 128>>>(P0, enc2_b, out_Z, slice, emb);

    // 3. decoder GAT layer (K=128): GEMM writes H16 only
    gemm2<128, 128, 2><<<dim3(4, 32, 1), 256, SM128>>>(
        A16, W3h, W3l, dec1_b, nullptr, KP_DEC, KP_DEC, HH1);
    feats2h<<<NN / 4, 512>>>(dec1_v0, dec1_v1);
    gat_agg4<<<NN, 128>>>();   // H16 -> g_A16 [4096,512]

    // 4. recon GEMM (K=512)
    gemm2<128, 128, 0><<<dim3(8, 32, 1), 256, SM128>>>(
        A16, W4h, W4l, dec2_b, out_recon, HH1, HH1, GG);
}

// round 17
// speedup vs baseline: 1.1117x; 1.0897x over previous
#include <cuda_runtime.h>
#include <cuda_fp16.h>
#include <math.h>
#include <stdint.h>

#define NN 4096
#define GG 1024
#define HH1 512
#define HH2 64
#define NHEAD 4
#define CHAN 128
#define SEDIM 16
#define CAP 256
#define KP_DEC 128

// ---------------- scratch (static device globals; no allocation) ----------
__device__ __half g_A16[NN * GG];          // activations, single fp16
__device__ __half g_H16[NN * HH1];         // GAT pre-activation H, fp16
__device__ __half g_W1h[HH1 * GG],     g_W1l[HH1 * GG];      // enc1 [512][1024]
__device__ __half g_W2h[HH2 * HH1],    g_W2l[HH2 * HH1];     // enc2 [64][512]
__device__ __half g_W3h[HH1 * KP_DEC], g_W3l[HH1 * KP_DEC];  // dec1 [512][128]
__device__ __half g_W4h[GG * HH1],     g_W4l[GG * HH1];      // dec2 [1024][512]
__device__ float g_P0[NN * GG];            // split-K partials (Z GEMM)
__device__ float g_f1[NHEAD * NN];
__device__ float g_f2[NHEAD * NN];
__device__ int   g_cols[NN * CAP];
__device__ int   g_cnt[NN];

// ---------------- helpers ---------------------------------------------------
__device__ __forceinline__ void hsplit(float x, __half* h, __half* l) {
    __half hh = __float2half_rn(x);
    *h = hh;
    *l = __float2half_rn(x - __half2float(hh));
}
__device__ __forceinline__ uint32_t smem_u32(const void* p) {
    uint32_t a;
    asm("{ .reg .u64 t; cvta.to.shared.u64 t, %1; cvt.u32.u64 %0, t; }" : "=r"(a) : "l"(p));
    return a;
}
#define LDM4(r, addr) \
    asm volatile("ldmatrix.sync.aligned.m8n8.x4.shared.b16 {%0,%1,%2,%3}, [%4];" \
                 : "=r"((r)[0]), "=r"((r)[1]), "=r"((r)[2]), "=r"((r)[3]) : "r"(addr))
#define MMAF16(d, a, b0_, b1_) \
    asm volatile("mma.sync.aligned.m16n8k16.row.col.f32.f16.f16.f32 " \
                 "{%0,%1,%2,%3}, {%4,%5,%6,%7}, {%8,%9}, {%0,%1,%2,%3};" \
                 : "+f"((d)[0]), "+f"((d)[1]), "+f"((d)[2]), "+f"((d)[3]) \
                 : "r"((a)[0]), "r"((a)[1]), "r"((a)[2]), "r"((a)[3]), "r"(b0_), "r"(b1_))
#define CP16(dst, src) \
    asm volatile("cp.async.cg.shared.global [%0], [%1], 16;" :: "r"(dst), "l"(src))

// ---------------- fused prologue: csr + A16 convert + all weight packs -----
__global__ void __launch_bounds__(256) prologue(
    const float* __restrict__ adj, const float4* __restrict__ node,
    const float* __restrict__ enc1_W, const float* __restrict__ enc2_W,
    const float* __restrict__ dec1_W, const float* __restrict__ dec2_W) {
    __shared__ int cnt;
    int b = blockIdx.x, tid = threadIdx.x;
    if (b < 4096) {
        if (tid == 0) cnt = 0;
        __syncthreads();
        const float4* arow = (const float4*)(adj + (size_t)b * NN);
        for (int j4 = tid; j4 < NN / 4; j4 += 256) {
            float4 v = arow[j4];
            if (v.x != 0.f) { int k = atomicAdd(&cnt, 1); if (k < CAP) g_cols[b * CAP + k] = j4 * 4 + 0; }
            if (v.y != 0.f) { int k = atomicAdd(&cnt, 1); if (k < CAP) g_cols[b * CAP + k] = j4 * 4 + 1; }
            if (v.z != 0.f) { int k = atomicAdd(&cnt, 1); if (k < CAP) g_cols[b * CAP + k] = j4 * 4 + 2; }
            if (v.w != 0.f) { int k = atomicAdd(&cnt, 1); if (k < CAP) g_cols[b * CAP + k] = j4 * 4 + 3; }
        }
        __syncthreads();
        if (tid == 0) g_cnt[b] = min(cnt, CAP);
    } else if (b < 8192) {
        int i = (b - 4096) * 256 + tid;          // over NN*GG/4
        float4 v = node[i];
        __half2 h0 = __floats2half2_rn(v.x, v.y);
        __half2 h1 = __floats2half2_rn(v.z, v.w);
        uint2 u;
        u.x = *reinterpret_cast<uint32_t*>(&h0);
        u.y = *reinterpret_cast<uint32_t*>(&h1);
        *(uint2*)(g_A16 + (size_t)i * 4) = u;
    } else if (b < 10240) {
        int idx = (b - 8192) * 256 + tid;
        int n = idx >> 10, k = idx & 1023;
        float v = enc1_W[((size_t)(n >> 7) * GG + k) * CHAN + (n & 127)];
        hsplit(v, &g_W1h[idx], &g_W1l[idx]);
    } else if (b < 10368) {
        int idx = (b - 10240) * 256 + tid;
        int n = idx >> 9, k = idx & 511;
        hsplit(enc2_W[k * HH2 + n], &g_W2h[idx], &g_W2l[idx]);
    } else if (b < 10624) {
        int idx = (b - 10368) * 256 + tid;
        int n = idx >> 7, k = idx & 127;
        float v = (k < HH2 + SEDIM)
                      ? dec1_W[((size_t)(n >> 7) * (HH2 + SEDIM) + k) * CHAN + (n & 127)]
                      : 0.f;
        hsplit(v, &g_W3h[idx], &g_W3l[idx]);
    } else {
        int idx = (b - 10624) * 256 + tid;
        int n = idx >> 9, k = idx & 511;
        hsplit(dec2_W[(size_t)k * GG + n], &g_W4h[idx], &g_W4l[idx]);
    }
}

// ---------------- fused Z reduce + decoder input build ---------------------
__global__ void __launch_bounds__(128) reduceZ(
    const float* __restrict__ P, const float* __restrict__ bias,
    float* __restrict__ outZ, const int* __restrict__ slice,
    const float* __restrict__ emb) {
    int n = blockIdx.x, t = threadIdx.x;   // 128 threads
    float v = 0.f;
    if (t < HH2) {
        int e = n * HH2 + t;
        v = P[e] + P[e + NN * HH2] + P[e + 2 * NN * HH2] + P[e + 3 * NN * HH2] + bias[t];
        outZ[e] = v;
    } else if (t < HH2 + SEDIM) {
        v = emb[slice[n] * SEDIM + (t - HH2)];
    }
    g_A16[(size_t)n * KP_DEC + t] = __float2half_rn(v);
}

// ---------------- HMMA fp16 GEMM, 3-stage pipeline, 1 sync/chunk ------------
// MODE 0: write C fp32 (+bias or raw partial).  MODE 2: write H16 only (+bias).
// TERMS: 2 = a*(Bh+Bl) split;  1 = a*Bh only (output-layer precision budget).
template <int MTILE, int NT, int MODE, int TERMS>
__global__ void __launch_bounds__(256, 2)
gemm2(const __half* __restrict__ A, const __half* __restrict__ Bh_,
      const __half* __restrict__ Bl_, const float* __restrict__ bias,
      float* __restrict__ C, int Kfull, int Ksplit, int Nc) {
    constexpr int WMW = 2;
    constexpr int WNW = 4;
    constexpr int WM  = MTILE / WMW;             // 64
    constexpr int WN  = NT / WNW;
    constexpr int MT  = WM / 16;                 // 4
    constexpr int NTL = WN / 8;
    constexpr int NP  = NTL / 2;
    constexpr int ASZ = MTILE * 80;
    constexpr int BSZ = NT * 80;
    constexpr int STG = ASZ + 2 * BSZ;
    constexpr int AJ  = MTILE / 64;              // 2
    constexpr int BJ  = NT / 64;

    extern __shared__ char sm[];
    const int tid = threadIdx.x, lane = tid & 31, wid = tid >> 5;
    const int m0 = blockIdx.y * MTILE, n0 = blockIdx.x * NT;
    const int koff = blockIdx.z * Ksplit;
    const int wm0 = (wid % WMW) * WM, wn0 = (wid / WMW) * WN;

    const int ar = tid >> 1, ac = (tid & 1) * 16;
    const size_t abase = (size_t)(m0 + ar) * Kfull + koff + ac;
    const int br = (BJ == 2) ? (tid >> 1) : (tid >> 2);
    const int bc = (BJ == 2) ? ((tid & 1) * 16) : ((tid & 3) * 8);
    const size_t bbase = (size_t)(n0 + br) * Kfull + koff + bc;

    const uint32_t sA = smem_u32(sm);
    const uint32_t stA = ar * 80 + ac * 2;
    const uint32_t stB = br * 80 + bc * 2;

    const int lr = lane & 15, lk = (lane >> 4) * 8;
    const uint32_t aoff = (wm0 + lr) * 80 + lk * 2;
    const uint32_t boff = (wn0 + lr) * 80 + lk * 2;

    float acc[MT][NTL][4];
#pragma unroll
    for (int i = 0; i < MT; i++)
#pragma unroll
        for (int j = 0; j < NTL; j++)
#pragma unroll
            for (int q = 0; q < 4; q++) acc[i][j][q] = 0.f;

    const int NC = Ksplit >> 5;

#define GLOADC(c0, buf)                                                        \
    {                                                                          \
        int k0 = (c0) * 32;                                                    \
        uint32_t d = sA + (buf) * STG;                                         \
        _Pragma("unroll") for (int j = 0; j < AJ; j++)                         \
            CP16(d + stA + j * 16, A + abase + k0 + j * 8);                    \
        _Pragma("unroll") for (int j = 0; j < BJ; j++) {                       \
            CP16(d + ASZ + stB + j * 16, Bh_ + bbase + k0 + j * 8);            \
            if (TERMS == 2)                                                    \
                CP16(d + ASZ + BSZ + stB + j * 16, Bl_ + bbase + k0 + j * 8);  \
        }                                                                      \
        asm volatile("cp.async.commit_group;" ::: "memory");                   \
    }

    GLOADC(0, 0);
    GLOADC(1, 1);
    for (int c = 0; c < NC; c++) {
        if (c + 1 < NC) {
            asm volatile("cp.async.wait_group 1;" ::: "memory");
        } else {
            asm volatile("cp.async.wait_group 0;" ::: "memory");
        }
        __syncthreads();
        int buf = c % 3;
        uint32_t uA  = sA + buf * STG;
        uint32_t uBh = uA + ASZ;
        uint32_t uBl = uBh + BSZ;
#pragma unroll
        for (int ks = 0; ks < 2; ks++) {
            uint32_t a_[MT][4], bh[NP][4], bl[NP][4];
#pragma unroll
            for (int mt = 0; mt < MT; mt++) LDM4(a_[mt], uA + aoff + mt * 1280 + ks * 32);
#pragma unroll
            for (int p = 0; p < NP; p++) LDM4(bh[p], uBh + boff + p * 1280 + ks * 32);
            if (TERMS == 2) {
#pragma unroll
                for (int p = 0; p < NP; p++) LDM4(bl[p], uBl + boff + p * 1280 + ks * 32);
            }
#pragma unroll
            for (int mt = 0; mt < MT; mt++)
#pragma unroll
                for (int p = 0; p < NP; p++) {
                    MMAF16(acc[mt][2 * p],     a_[mt], bh[p][0], bh[p][2]);
                    MMAF16(acc[mt][2 * p + 1], a_[mt], bh[p][1], bh[p][3]);
                }
            if (TERMS == 2) {
#pragma unroll
                for (int mt = 0; mt < MT; mt++)
#pragma unroll
                    for (int p = 0; p < NP; p++) {
                        MMAF16(acc[mt][2 * p],     a_[mt], bl[p][0], bl[p][2]);
                        MMAF16(acc[mt][2 * p + 1], a_[mt], bl[p][1], bl[p][3]);
                    }
            }
        }
        if (c + 2 < NC) GLOADC(c + 2, (c + 2) % 3);
    }
#undef GLOADC

    // epilogue
    float* Cz = C + (size_t)blockIdx.z * NN * Nc;
    int g = lane >> 2, tg = lane & 3;
#pragma unroll
    for (int mt = 0; mt < MT; mt++) {
        int row = m0 + wm0 + mt * 16 + g;
#pragma unroll
        for (int nt = 0; nt < NTL; nt++) {
            int col = n0 + wn0 + nt * 8 + tg * 2;
            float b0 = bias ? bias[col] : 0.f, b1 = bias ? bias[col + 1] : 0.f;
            float c0 = acc[mt][nt][0] + b0, c1 = acc[mt][nt][1] + b1;
            float c2 = acc[mt][nt][2] + b0, c3 = acc[mt][nt][3] + b1;
            if (MODE == 0) {
                Cz[(size_t)row * Nc + col]           = c0;
                Cz[(size_t)row * Nc + col + 1]       = c1;
                Cz[(size_t)(row + 8) * Nc + col]     = c2;
                Cz[(size_t)(row + 8) * Nc + col + 1] = c3;
            } else {
                __half2 p0 = __floats2half2_rn(c0, c1);
                __half2 p1 = __floats2half2_rn(c2, c3);
                *(uint32_t*)(g_H16 + (size_t)row * Nc + col) =
                    *reinterpret_cast<uint32_t*>(&p0);
                *(uint32_t*)(g_H16 + (size_t)(row + 8) * Nc + col) =
                    *reinterpret_cast<uint32_t*>(&p1);
            }
        }
    }
}

// ---------------- attention features from fp16 H ---------------------------
__global__ void __launch_bounds__(512) feats2h(const float* __restrict__ v0,
                                               const float* __restrict__ v1) {
    int tid = threadIdx.x, wid = tid >> 5, lid = tid & 31;
    int n = blockIdx.x * 4 + (wid >> 2);
    int h = wid & 3;
    uint2 uv = *(const uint2*)(g_H16 + (size_t)n * HH1 + h * CHAN + lid * 4);
    float2 f0 = __half22float2(*reinterpret_cast<__half2*>(&uv.x));
    float2 f1v = __half22float2(*reinterpret_cast<__half2*>(&uv.y));
    float4 a = *(const float4*)(v0 + h * CHAN + lid * 4);
    float4 b = *(const float4*)(v1 + h * CHAN + lid * 4);
    float s1 = f0.x * a.x + f0.y * a.y + f1v.x * a.z + f1v.y * a.w;
    float s2 = f0.x * b.x + f0.y * b.y + f1v.x * b.z + f1v.y * b.w;
#pragma unroll
    for (int o = 16; o > 0; o >>= 1) {
        s1 += __shfl_down_sync(0xffffffffu, s1, o);
        s2 += __shfl_down_sync(0xffffffffu, s2, o);
    }
    if (lid == 0) {
        g_f1[h * NN + n] = s1;
        g_f2[h * NN + n] = s2;
    }
}

// ---------------- sparse attention softmax + aggregation + ELU -------------
__global__ void __launch_bounds__(128) gat_agg4() {
    int row = blockIdx.x, tid = threadIdx.x, wid = tid >> 5, lid = tid & 31;
    int cnt = g_cnt[row];
    const int* cols = g_cols + row * CAP;
    const float* f2h = g_f2 + wid * NN;
    float f1r = g_f1[wid * NN + row];
    const __half* Hb = g_H16 + wid * CHAN + lid * 4;
    float4 acc = {0.f, 0.f, 0.f, 0.f};
    float inv;

    if (cnt <= 32) {
        bool valid = lid < cnt;
        int col = valid ? cols[lid] : 0;
        float u = 0.f;
        if (valid) {
            float x = f1r + f2h[col];
            u = 1.f / (1.f + expf(-x)) - 0.5f;
        }
        float mv = (valid && u != 0.f) ? u : -1e30f;
#pragma unroll
        for (int o = 16; o; o >>= 1) mv = fmaxf(mv, __shfl_xor_sync(0xffffffffu, mv, o));
        float e = (valid && u != 0.f) ? expf(u - mv) : 0.f;
        float s = e;
#pragma unroll
        for (int o = 16; o; o >>= 1) s += __shfl_xor_sync(0xffffffffu, s, o);
        inv = 1.f / fmaxf(s, 1e-30f);
        uint32_t pk = ((uint32_t)__half_as_ushort(__float2half_rn(e)) << 16) |
                      (uint32_t)col;
        for (int k = 0; k < cnt; k++) {
            uint32_t p = __shfl_sync(0xffffffffu, pk, k);
            if (p >> 16) {
                float w = __half2float(__ushort_as_half((unsigned short)(p >> 16)));
                int c2 = p & 0xFFFF;
                uint2 uv = *(const uint2*)(Hb + (size_t)c2 * HH1);
                float2 f0 = __half22float2(*reinterpret_cast<__half2*>(&uv.x));
                float2 f1v = __half22float2(*reinterpret_cast<__half2*>(&uv.y));
                acc.x += w * f0.x; acc.y += w * f0.y;
                acc.z += w * f1v.x; acc.w += w * f1v.y;
            }
        }
    } else {
        float mv = -1e30f;
        for (int c0 = 0; c0 < cnt; c0 += 32) {
            int k = c0 + lid;
            if (k < cnt) {
                float x = f1r + f2h[cols[k]];
                float u = 1.f / (1.f + expf(-x)) - 0.5f;
                if (u != 0.f) mv = fmaxf(mv, u);
            }
        }
#pragma unroll
        for (int o = 16; o; o >>= 1) mv = fmaxf(mv, __shfl_xor_sync(0xffffffffu, mv, o));
        float s = 0.f;
        for (int c0 = 0; c0 < cnt; c0 += 32) {
            int k = c0 + lid;
            if (k < cnt) {
                float x = f1r + f2h[cols[k]];
                float u = 1.f / (1.f + expf(-x)) - 0.5f;
                if (u != 0.f) s += expf(u - mv);
            }
        }
#pragma unroll
        for (int o = 16; o; o >>= 1) s += __shfl_xor_sync(0xffffffffu, s, o);
        inv = 1.f / fmaxf(s, 1e-30f);
        for (int c0 = 0; c0 < cnt; c0 += 32) {
            int k = c0 + lid;
            int col = (k < cnt) ? cols[k] : 0;
            float e = 0.f;
            if (k < cnt) {
                float x = f1r + f2h[col];
                float u = 1.f / (1.f + expf(-x)) - 0.5f;
                if (u != 0.f) e = expf(u - mv);
            }
            int lim = min(32, cnt - c0);
            for (int j = 0; j < lim; j++) {
                float w = __shfl_sync(0xffffffffu, e, j);
                int c2 = __shfl_sync(0xffffffffu, col, j);
                if (w != 0.f) {
                    uint2 uv = *(const uint2*)(Hb + (size_t)c2 * HH1);
                    float2 f0 = __half22float2(*reinterpret_cast<__half2*>(&uv.x));
                    float2 f1v = __half22float2(*reinterpret_cast<__half2*>(&uv.y));
                    acc.x += w * f0.x; acc.y += w * f0.y;
                    acc.z += w * f1v.x; acc.w += w * f1v.y;
                }
            }
        }
    }

    acc.x *= inv; acc.y *= inv; acc.z *= inv; acc.w *= inv;
    acc.x = (acc.x > 0.f) ? acc.x : expm1f(acc.x);
    acc.y = (acc.y > 0.f) ? acc.y : expm1f(acc.y);
    acc.z = (acc.z > 0.f) ? acc.z : expm1f(acc.z);
    acc.w = (acc.w > 0.f) ? acc.w : expm1f(acc.w);
    __half2 p0 = __floats2half2_rn(acc.x, acc.y);
    __half2 p1 = __floats2half2_rn(acc.z, acc.w);
    uint2 u;
    u.x = *reinterpret_cast<uint32_t*>(&p0);
    u.y = *reinterpret_cast<uint32_t*>(&p1);
    *(uint2*)(g_A16 + (size_t)row * HH1 + wid * CHAN + lid * 4) = u;
}

extern "C" void kernel_launch(void* const* d_in, const int* in_sizes, int n_in,
                              void* d_out, int out_size) {
    const float* adj     = (const float*)d_in[0];
    const float* node    = (const float*)d_in[1];
    const int*   slice   = (const int*)d_in[4];
    const float* enc1_W  = (const float*)d_in[6];
    const float* enc1_b  = (const float*)d_in[7];
    const float* enc1_v0 = (const float*)d_in[8];
    const float* enc1_v1 = (const float*)d_in[9];
    const float* enc2_W  = (const float*)d_in[10];
    const float* enc2_b  = (const float*)d_in[11];
    const float* dec1_W  = (const float*)d_in[12];
    const float* dec1_b  = (const float*)d_in[13];
    const float* dec1_v0 = (const float*)d_in[14];
    const float* dec1_v1 = (const float*)d_in[15];
    const float* dec2_W  = (const float*)d_in[16];
    const float* dec2_b  = (const float*)d_in[17];
    const float* emb     = (const float*)d_in[18];

    float* out_recon = (float*)d_out;                   // [N, G]
    float* out_Z     = (float*)d_out + (size_t)NN * GG; // [N, H2]

    float* P0;   cudaGetSymbolAddress((void**)&P0, g_P0);
    __half* A16; cudaGetSymbolAddress((void**)&A16, g_A16);
    __half* W1h; cudaGetSymbolAddress((void**)&W1h, g_W1h);
    __half* W1l; cudaGetSymbolAddress((void**)&W1l, g_W1l);
    __half* W2h; cudaGetSymbolAddress((void**)&W2h, g_W2h);
    __half* W2l; cudaGetSymbolAddress((void**)&W2l, g_W2l);
    __half* W3h; cudaGetSymbolAddress((void**)&W3h, g_W3h);
    __half* W3l; cudaGetSymbolAddress((void**)&W3l, g_W3l);
    __half* W4h; cudaGetSymbolAddress((void**)&W4h, g_W4h);
    __half* W4l; cudaGetSymbolAddress((void**)&W4l, g_W4l);

    const int SM128 = 3 * (128 * 80 + 2 * 128 * 80); // 92160
    const int SM64  = 3 * (128 * 80 + 2 * 64 * 80);  // 61440
    cudaFuncSetAttribute((const void*)gemm2<128, 128, 0, 1>,
                         cudaFuncAttributeMaxDynamicSharedMemorySize, SM128);
    cudaFuncSetAttribute((const void*)gemm2<128, 128, 2, 2>,
                         cudaFuncAttributeMaxDynamicSharedMemorySize, SM128);
    cudaFuncSetAttribute((const void*)gemm2<128, 64, 0, 2>,
                         cudaFuncAttributeMaxDynamicSharedMemorySize, SM64);

    // 0. fused prologue: CSR + fp16 convert + all weight packs
    prologue<<<12672, 256>>>(adj, (const float4*)node,
                             enc1_W, enc2_W, dec1_W, dec2_W);

    // 1. enc1 GEMM (K=1024, no split-K) -> H16; feats from H16
    gemm2<128, 128, 2, 2><<<dim3(4, 32, 1), 256, SM128>>>(
        A16, W1h, W1l, enc1_b, nullptr, GG, GG, HH1);
    feats2h<<<NN / 4, 512>>>(enc1_v0, enc1_v1);
    gat_agg4<<<NN, 128>>>();   // H16 -> g_A16 [4096,512] fp16

    // 2. Z GEMM (K=512, split-K=4) + fused reduce -> out_Z + decoder input
    gemm2<128, 64, 0, 2><<<dim3(1, 32, 4), 256, SM64>>>(
        A16, W2h, W2l, nullptr, P0, HH1, HH1 / 4, HH2);
    reduceZ<<<NN, 128>>>(P0, enc2_b, out_Z, slice, emb);

    // 3. decoder GAT layer (K=128): GEMM writes H16 only
    gemm2<128, 128, 2, 2><<<dim3(4, 32, 1), 256, SM128>>>(
        A16, W3h, W3l, dec1_b, nullptr, KP_DEC, KP_DEC, HH1);
    feats2h<<<NN / 4, 512>>>(dec1_v0, dec1_v1);
    gat_agg4<<<NN, 128>>>();   // H16 -> g_A16 [4096,512]

    // 4. recon GEMM (K=512): 1-term (output layer, error budget allows)
    gemm2<128, 128, 0, 1><<<dim3(8, 32, 1), 256, SM128>>>(
        A16, W4h, W4l, dec2_b, out_recon, HH1, HH1, GG);
}